// round 1
// baseline (speedup 1.0000x reference)
#include <cuda_runtime.h>
#include <math.h>

#define H   1032
#define INW 2064
#define G3  3096
#define SL  8192
#define V   50257

// d_out layout (tuple order, flattened): output(V), attn_context(H), hidden(H), attn_w(S)
#define OUT_LOGITS 0
#define OUT_CTX    50257
#define OUT_HID    51289
#define OUT_ATTNW  52321

// scratch (device globals; all fully rewritten/zeroed each replay)
__device__ float g_gx[G3];
__device__ float g_gh[G3];
__device__ float g_hnew[H];
__device__ __align__(16) float g_v[H];
__device__ float g_c0;
__device__ float g_scores[SL];
__device__ float g_ctx[H];
__device__ __align__(16) float g_joined[INW];
__device__ float g_lse;

// ---------------- K1: gx = W_ih @ [emb[word], last_ctx] + b_ih ; gh = W_hh @ h + b_hh
__global__ void k_gates(const int* __restrict__ word, const float* __restrict__ lctx,
                        const float* __restrict__ hprev, const float* __restrict__ emb,
                        const float* __restrict__ W_ih, const float* __restrict__ W_hh,
                        const float* __restrict__ b_ih, const float* __restrict__ b_hh) {
    int warp = (blockIdx.x * blockDim.x + threadIdx.x) >> 5;
    int lane = threadIdx.x & 31;
    if (warp < G3) {
        int row = warp;
        const float4* w4 = (const float4*)(W_ih + (size_t)row * INW);
        const float4* e4 = (const float4*)(emb + (size_t)word[0] * H);
        const float4* c4 = (const float4*)lctx;
        float s = 0.f;
        for (int k = lane; k < INW / 4; k += 32) {
            float4 w = w4[k];
            float4 a = (k < H / 4) ? e4[k] : c4[k - H / 4];
            s += w.x * a.x + w.y * a.y + w.z * a.z + w.w * a.w;
        }
        #pragma unroll
        for (int o = 16; o; o >>= 1) s += __shfl_xor_sync(0xffffffffu, s, o);
        if (lane == 0) g_gx[row] = s + b_ih[row];
    } else if (warp < 2 * G3) {
        int row = warp - G3;
        const float4* w4 = (const float4*)(W_hh + (size_t)row * H);
        const float4* h4 = (const float4*)hprev;
        float s = 0.f;
        for (int k = lane; k < H / 4; k += 32) {
            float4 w = w4[k]; float4 a = h4[k];
            s += w.x * a.x + w.y * a.y + w.z * a.z + w.w * a.w;
        }
        #pragma unroll
        for (int o = 16; o; o >>= 1) s += __shfl_xor_sync(0xffffffffu, s, o);
        if (lane == 0) g_gh[row] = s + b_hh[row];
    }
}

// ---------------- K2: GRU combine -> h_new; also zero accumulators; c0 = b_a . h_new
__global__ void k_gru(const float* __restrict__ hprev, const float* __restrict__ b_a,
                      float* __restrict__ d_out) {
    __shared__ float acc;
    int tid = threadIdx.x;
    if (tid == 0) acc = 0.f;
    __syncthreads();
    float part = 0.f;
    for (int i = tid; i < H; i += blockDim.x) {
        float r = 1.f / (1.f + expf(-(g_gx[i] + g_gh[i])));
        float z = 1.f / (1.f + expf(-(g_gx[i + H] + g_gh[i + H])));
        float n = tanhf(g_gx[i + 2 * H] + r * g_gh[i + 2 * H]);
        float h = hprev[i];
        float hn = (1.f - z) * n + z * h;
        g_hnew[i] = hn;
        d_out[OUT_HID + i] = hn;
        g_v[i] = 0.f;
        g_ctx[i] = 0.f;
        part += b_a[i] * hn;
    }
    #pragma unroll
    for (int o = 16; o; o >>= 1) part += __shfl_xor_sync(0xffffffffu, part, o);
    if ((tid & 31) == 0) atomicAdd(&acc, part);
    __syncthreads();
    if (tid == 0) g_c0 = acc;
}

// ---------------- K3: v[k] = sum_j W_a[j,k] * h_new[j]   (v = W_a^T h_new)
__global__ void k_va(const float* __restrict__ W_a) {
    int k = blockIdx.x * 128 + threadIdx.x;     // 9 strips of 128 over k
    int j0 = blockIdx.y * 129;                  // 8 chunks of 129 over j
    if (k >= H) return;
    float p = 0.f;
    for (int j = j0; j < j0 + 129; ++j)
        p += W_a[(size_t)j * H + k] * g_hnew[j];
    atomicAdd(&g_v[k], p);
}

// ---------------- K4: scores[s] = enc[s] . v + c0
__global__ void k_scores(const float* __restrict__ enc) {
    int warp = (blockIdx.x * blockDim.x + threadIdx.x) >> 5;
    int lane = threadIdx.x & 31;
    if (warp >= SL) return;
    const float4* e4 = (const float4*)(enc + (size_t)warp * H);
    const float4* v4 = (const float4*)g_v;
    float s = 0.f;
    for (int k = lane; k < H / 4; k += 32) {
        float4 a = e4[k]; float4 b = v4[k];
        s += a.x * b.x + a.y * b.y + a.z * b.z + a.w * b.w;
    }
    #pragma unroll
    for (int o = 16; o; o >>= 1) s += __shfl_xor_sync(0xffffffffu, s, o);
    if (lane == 0) g_scores[warp] = s + g_c0;
}

// ---------------- K5: softmax over 8192 scores -> attn_w in d_out
__global__ void k_softmax(float* __restrict__ d_out) {
    __shared__ float red[32];
    int tid = threadIdx.x;
    float vals[8];
    float m = -1e30f;
    #pragma unroll
    for (int u = 0; u < 8; u++) { vals[u] = g_scores[tid + u * 1024]; m = fmaxf(m, vals[u]); }
    #pragma unroll
    for (int o = 16; o; o >>= 1) m = fmaxf(m, __shfl_xor_sync(0xffffffffu, m, o));
    if ((tid & 31) == 0) red[tid >> 5] = m;
    __syncthreads();
    if (tid < 32) {
        float t = red[tid];
        #pragma unroll
        for (int o = 16; o; o >>= 1) t = fmaxf(t, __shfl_xor_sync(0xffffffffu, t, o));
        if (tid == 0) red[0] = t;
    }
    __syncthreads();
    m = red[0];
    __syncthreads();
    float ssum = 0.f;
    #pragma unroll
    for (int u = 0; u < 8; u++) { vals[u] = expf(vals[u] - m); ssum += vals[u]; }
    #pragma unroll
    for (int o = 16; o; o >>= 1) ssum += __shfl_xor_sync(0xffffffffu, ssum, o);
    if ((tid & 31) == 0) red[tid >> 5] = ssum;
    __syncthreads();
    if (tid < 32) {
        float t = red[tid];
        #pragma unroll
        for (int o = 16; o; o >>= 1) t += __shfl_xor_sync(0xffffffffu, t, o);
        if (tid == 0) red[0] = t;
    }
    __syncthreads();
    float inv = 1.f / red[0];
    #pragma unroll
    for (int u = 0; u < 8; u++)
        d_out[OUT_ATTNW + tid + u * 1024] = vals[u] * inv;
}

// ---------------- K6: context[j] = sum_s w[s] * enc[s][j]  (partials + atomics)
__global__ void k_context(const float* __restrict__ enc, const float* __restrict__ d_out) {
    int s0 = blockIdx.x * 64;                 // 128 blocks x 64 rows
    int tid = threadIdx.x;                    // 256 threads
    float a0 = 0, a1 = 0, a2 = 0, a3 = 0, a4 = 0;
    for (int s = s0; s < s0 + 64; ++s) {
        float w = __ldg(&d_out[OUT_ATTNW + s]);
        const float* row = enc + (size_t)s * H;
        a0 += w * row[tid];
        a1 += w * row[tid + 256];
        a2 += w * row[tid + 512];
        a3 += w * row[tid + 768];
        if (tid < 8) a4 += w * row[tid + 1024];
    }
    atomicAdd(&g_ctx[tid], a0);
    atomicAdd(&g_ctx[tid + 256], a1);
    atomicAdd(&g_ctx[tid + 512], a2);
    atomicAdd(&g_ctx[tid + 768], a3);
    if (tid < 8) atomicAdd(&g_ctx[tid + 1024], a4);
}

// ---------------- K7: emit attn_context, build joined = [h_new, context]
__global__ void k_join(float* __restrict__ d_out) {
    int i = blockIdx.x * blockDim.x + threadIdx.x;
    if (i < H) {
        float c = g_ctx[i];
        d_out[OUT_CTX + i] = c;
        g_joined[i] = g_hnew[i];
        g_joined[H + i] = c;
    }
}

// ---------------- K8: logits = W_out @ joined + b_out   (415 MB stream, warp-per-row)
__global__ void k_out(const float* __restrict__ W_out, const float* __restrict__ b_out,
                      float* __restrict__ d_out) {
    __shared__ __align__(16) float sj[INW];
    for (int i = threadIdx.x; i < INW; i += blockDim.x) sj[i] = g_joined[i];
    __syncthreads();
    int warp = (blockIdx.x * blockDim.x + threadIdx.x) >> 5;
    int lane = threadIdx.x & 31;
    if (warp >= V) return;
    const float4* w4 = (const float4*)(W_out + (size_t)warp * INW);
    const float4* j4 = (const float4*)sj;
    float s = 0.f;
    for (int k = lane; k < INW / 4; k += 32) {
        float4 a = w4[k]; float4 b = j4[k];
        s += a.x * b.x + a.y * b.y + a.z * b.z + a.w * b.w;
    }
    #pragma unroll
    for (int o = 16; o; o >>= 1) s += __shfl_xor_sync(0xffffffffu, s, o);
    if (lane == 0) d_out[warp] = s + b_out[warp];
}

// ---------------- K9: logsumexp scalar over logits
__global__ void k_lse(const float* __restrict__ d_out) {
    __shared__ float red[32];
    int tid = threadIdx.x;
    float m = -1e30f;
    for (int i = tid; i < V; i += 1024) m = fmaxf(m, d_out[i]);
    #pragma unroll
    for (int o = 16; o; o >>= 1) m = fmaxf(m, __shfl_xor_sync(0xffffffffu, m, o));
    if ((tid & 31) == 0) red[tid >> 5] = m;
    __syncthreads();
    if (tid < 32) {
        float t = red[tid];
        #pragma unroll
        for (int o = 16; o; o >>= 1) t = fmaxf(t, __shfl_xor_sync(0xffffffffu, t, o));
        if (tid == 0) red[0] = t;
    }
    __syncthreads();
    m = red[0];
    __syncthreads();
    float ssum = 0.f;
    for (int i = tid; i < V; i += 1024) ssum += expf(d_out[i] - m);
    #pragma unroll
    for (int o = 16; o; o >>= 1) ssum += __shfl_xor_sync(0xffffffffu, ssum, o);
    if ((tid & 31) == 0) red[tid >> 5] = ssum;
    __syncthreads();
    if (tid < 32) {
        float t = red[tid];
        #pragma unroll
        for (int o = 16; o; o >>= 1) t += __shfl_xor_sync(0xffffffffu, t, o);
        if (tid == 0) red[0] = t;
    }
    __syncthreads();
    if (tid == 0) g_lse = m + logf(red[0]);
}

// ---------------- K10: output = logits - lse (in place)
__global__ void k_final(float* __restrict__ d_out) {
    int i = blockIdx.x * blockDim.x + threadIdx.x;
    if (i < V) d_out[i] -= g_lse;
}

extern "C" void kernel_launch(void* const* d_in, const int* in_sizes, int n_in,
                              void* d_out, int out_size) {
    const int*   word  = (const int*)  d_in[0];
    const float* lctx  = (const float*)d_in[1];
    const float* hprev = (const float*)d_in[2];
    const float* enc   = (const float*)d_in[3];
    const float* emb   = (const float*)d_in[4];
    const float* W_ih  = (const float*)d_in[5];
    const float* W_hh  = (const float*)d_in[6];
    const float* b_ih  = (const float*)d_in[7];
    const float* b_hh  = (const float*)d_in[8];
    const float* W_a   = (const float*)d_in[9];
    const float* b_a   = (const float*)d_in[10];
    const float* W_out = (const float*)d_in[11];
    const float* b_out = (const float*)d_in[12];
    float* out = (float*)d_out;

    k_gates  <<<(2 * G3 * 32 + 255) / 256, 256>>>(word, lctx, hprev, emb, W_ih, W_hh, b_ih, b_hh);
    k_gru    <<<1, 1024>>>(hprev, b_a, out);
    k_va     <<<dim3(9, 8), 128>>>(W_a);
    k_scores <<<(SL * 32) / 256, 256>>>(enc);
    k_softmax<<<1, 1024>>>(out);
    k_context<<<128, 256>>>(enc, out);
    k_join   <<<(H + 255) / 256, 256>>>(out);
    k_out    <<<(V * 32 + 255) / 256, 256>>>(W_out, b_out, out);
    k_lse    <<<1, 1024>>>(out);
    k_final  <<<(V + 255) / 256, 256>>>(out);
}

// round 2
// speedup vs baseline: 1.0630x; 1.0630x over previous
#include <cuda_runtime.h>
#include <math.h>

#define H   1032
#define INW 2064
#define G3  3096
#define SL  8192
#define V   50257

// d_out layout (tuple order, flattened): output(V), attn_context(H), hidden(H), attn_w(S)
#define OUT_CTX    50257
#define OUT_HID    51289
#define OUT_ATTNW  52321

// scratch (device globals; fully rewritten each replay)
__device__ float g_gx[G3];
__device__ float g_gh[G3];
__device__ __align__(16) float g_hnew[H];
__device__ __align__(16) float g_v[H];
__device__ float g_c0;
__device__ float g_scores[SL];
__device__ float g_ctx[H];
__device__ __align__(16) float g_joined[INW];
__device__ float g_lse;

__device__ __forceinline__ float dot4(float4 a, float4 b) {
    return a.x * b.x + a.y * b.y + a.z * b.z + a.w * b.w;
}

__device__ __forceinline__ float warp_red(float s) {
    #pragma unroll
    for (int o = 16; o; o >>= 1) s += __shfl_xor_sync(0xffffffffu, s, o);
    return s;
}

// 516-float4 row dot against smem vector: fully unrolled, 4 accumulators.
__device__ __forceinline__ float row_dot_516(const float4* __restrict__ w4,
                                             const float4* __restrict__ x4, int lane) {
    float s0 = 0.f, s1 = 0.f, s2 = 0.f, s3 = 0.f;
    #pragma unroll
    for (int i = 0; i < 16; i += 4) {
        float4 a = w4[lane + 32 * (i + 0)];
        float4 b = w4[lane + 32 * (i + 1)];
        float4 c = w4[lane + 32 * (i + 2)];
        float4 d = w4[lane + 32 * (i + 3)];
        s0 += dot4(a, x4[lane + 32 * (i + 0)]);
        s1 += dot4(b, x4[lane + 32 * (i + 1)]);
        s2 += dot4(c, x4[lane + 32 * (i + 2)]);
        s3 += dot4(d, x4[lane + 32 * (i + 3)]);
    }
    if (lane < 4) s0 += dot4(w4[512 + lane], x4[512 + lane]);
    return (s0 + s1) + (s2 + s3);
}

// 258-float4 row dot against smem vector.
__device__ __forceinline__ float row_dot_258(const float4* __restrict__ w4,
                                             const float4* __restrict__ x4, int lane) {
    float s0 = 0.f, s1 = 0.f, s2 = 0.f, s3 = 0.f;
    #pragma unroll
    for (int i = 0; i < 8; i += 4) {
        float4 a = w4[lane + 32 * (i + 0)];
        float4 b = w4[lane + 32 * (i + 1)];
        float4 c = w4[lane + 32 * (i + 2)];
        float4 d = w4[lane + 32 * (i + 3)];
        s0 += dot4(a, x4[lane + 32 * (i + 0)]);
        s1 += dot4(b, x4[lane + 32 * (i + 1)]);
        s2 += dot4(c, x4[lane + 32 * (i + 2)]);
        s3 += dot4(d, x4[lane + 32 * (i + 3)]);
    }
    if (lane < 2) s0 += dot4(w4[256 + lane], x4[256 + lane]);
    return (s0 + s1) + (s2 + s3);
}

#define IH_BLOCKS 387   // 3096 rows / 8 warps

// ---------------- K1: gates. Blocks [0,387): gx rows; [387,774): gh rows.
__global__ void k_gates(const int* __restrict__ word, const float* __restrict__ lctx,
                        const float* __restrict__ hprev, const float* __restrict__ emb,
                        const float* __restrict__ W_ih, const float* __restrict__ W_hh,
                        const float* __restrict__ b_ih, const float* __restrict__ b_hh) {
    __shared__ __align__(16) float sx[INW];
    int lane = threadIdx.x & 31;
    int wib  = threadIdx.x >> 5;
    if (blockIdx.x < IH_BLOCKS) {
        const float* erow = emb + (size_t)word[0] * H;
        for (int i = threadIdx.x; i < INW; i += blockDim.x)
            sx[i] = (i < H) ? erow[i] : lctx[i - H];
        __syncthreads();
        int row = blockIdx.x * 8 + wib;
        float s = row_dot_516((const float4*)(W_ih + (size_t)row * INW),
                              (const float4*)sx, lane);
        s = warp_red(s);
        if (lane == 0) g_gx[row] = s + b_ih[row];
    } else {
        for (int i = threadIdx.x; i < H; i += blockDim.x) sx[i] = hprev[i];
        __syncthreads();
        int row = (blockIdx.x - IH_BLOCKS) * 8 + wib;
        float s = row_dot_258((const float4*)(W_hh + (size_t)row * H),
                              (const float4*)sx, lane);
        s = warp_red(s);
        if (lane == 0) g_gh[row] = s + b_hh[row];
    }
}

// ---------------- K2: GRU combine -> h_new; zero accumulators; c0 = b_a . h_new
__global__ void k_gru(const float* __restrict__ hprev, const float* __restrict__ b_a,
                      float* __restrict__ d_out) {
    __shared__ float acc;
    int tid = threadIdx.x;
    if (tid == 0) acc = 0.f;
    __syncthreads();
    float part = 0.f;
    for (int i = tid; i < H; i += blockDim.x) {
        float r = 1.f / (1.f + expf(-(g_gx[i] + g_gh[i])));
        float z = 1.f / (1.f + expf(-(g_gx[i + H] + g_gh[i + H])));
        float n = tanhf(g_gx[i + 2 * H] + r * g_gh[i + 2 * H]);
        float h = hprev[i];
        float hn = (1.f - z) * n + z * h;
        g_hnew[i] = hn;
        d_out[OUT_HID + i] = hn;
        g_joined[i] = hn;
        g_v[i] = 0.f;
        g_ctx[i] = 0.f;
        part += b_a[i] * hn;
    }
    part = warp_red(part);
    if ((tid & 31) == 0) atomicAdd(&acc, part);
    __syncthreads();
    if (tid == 0) g_c0 = acc;
}

// ---------------- K3: v[k] = sum_j W_a[j,k] * h_new[j]   (v = W_a^T h_new)
__global__ void k_va(const float* __restrict__ W_a) {
    int k = blockIdx.x * 128 + threadIdx.x;
    int j0 = blockIdx.y * 129;
    if (k >= H) return;
    float p0 = 0.f, p1 = 0.f, p2 = 0.f;
    int j = j0;
    #pragma unroll 3
    for (int u = 0; u < 43; ++u, j += 3) {
        p0 += W_a[(size_t)(j + 0) * H + k] * g_hnew[j + 0];
        p1 += W_a[(size_t)(j + 1) * H + k] * g_hnew[j + 1];
        p2 += W_a[(size_t)(j + 2) * H + k] * g_hnew[j + 2];
    }
    atomicAdd(&g_v[k], p0 + p1 + p2);
}

// ---------------- K4: scores[s] = enc[s] . v + c0
__global__ void k_scores(const float* __restrict__ enc) {
    __shared__ __align__(16) float sv[H];
    for (int i = threadIdx.x; i < H; i += blockDim.x) sv[i] = g_v[i];
    __syncthreads();
    int lane = threadIdx.x & 31;
    int row = blockIdx.x * 8 + (threadIdx.x >> 5);
    float s = row_dot_258((const float4*)(enc + (size_t)row * H),
                          (const float4*)sv, lane);
    s = warp_red(s);
    if (lane == 0) g_scores[row] = s + g_c0;
}

// ---------------- K5: softmax over 8192 scores -> attn_w in d_out
__global__ void k_softmax(float* __restrict__ d_out) {
    __shared__ float red[32];
    int tid = threadIdx.x;
    float vals[8];
    float m = -1e30f;
    #pragma unroll
    for (int u = 0; u < 8; u++) { vals[u] = g_scores[tid + u * 1024]; m = fmaxf(m, vals[u]); }
    #pragma unroll
    for (int o = 16; o; o >>= 1) m = fmaxf(m, __shfl_xor_sync(0xffffffffu, m, o));
    if ((tid & 31) == 0) red[tid >> 5] = m;
    __syncthreads();
    if (tid < 32) {
        float t = red[tid];
        #pragma unroll
        for (int o = 16; o; o >>= 1) t = fmaxf(t, __shfl_xor_sync(0xffffffffu, t, o));
        if (tid == 0) red[0] = t;
    }
    __syncthreads();
    m = red[0];
    __syncthreads();
    float ssum = 0.f;
    #pragma unroll
    for (int u = 0; u < 8; u++) { vals[u] = expf(vals[u] - m); ssum += vals[u]; }
    ssum = warp_red(ssum);
    if ((tid & 31) == 0) red[tid >> 5] = ssum;
    __syncthreads();
    if (tid < 32) {
        float t = red[tid];
        t = warp_red(t);
        if (tid == 0) red[0] = t;
    }
    __syncthreads();
    float inv = 1.f / red[0];
    #pragma unroll
    for (int u = 0; u < 8; u++)
        d_out[OUT_ATTNW + tid + u * 1024] = vals[u] * inv;
}

// ---------------- K6: context[j] = sum_s w[s] * enc[s][j]
__global__ void k_context(const float* __restrict__ enc, const float* __restrict__ d_out) {
    int s0 = blockIdx.x * 64;
    int tid = threadIdx.x;
    float a0 = 0, a1 = 0, a2 = 0, a3 = 0, a4 = 0;
    for (int s = s0; s < s0 + 64; ++s) {
        float w = __ldg(&d_out[OUT_ATTNW + s]);
        const float* row = enc + (size_t)s * H;
        a0 += w * row[tid];
        a1 += w * row[tid + 256];
        a2 += w * row[tid + 512];
        a3 += w * row[tid + 768];
        if (tid < 8) a4 += w * row[tid + 1024];
    }
    atomicAdd(&g_ctx[tid], a0);
    atomicAdd(&g_ctx[tid + 256], a1);
    atomicAdd(&g_ctx[tid + 512], a2);
    atomicAdd(&g_ctx[tid + 768], a3);
    if (tid < 8) atomicAdd(&g_ctx[tid + 1024], a4);
}

// ---------------- K7: emit attn_context, finish joined = [h_new, context]
__global__ void k_join(float* __restrict__ d_out) {
    int i = blockIdx.x * blockDim.x + threadIdx.x;
    if (i < H) {
        float c = g_ctx[i];
        d_out[OUT_CTX + i] = c;
        g_joined[H + i] = c;
    }
}

// ---------------- K8: logits = W_out @ joined + b_out   (415 MB stream)
__global__ void k_out(const float* __restrict__ W_out, const float* __restrict__ b_out,
                      float* __restrict__ d_out) {
    __shared__ __align__(16) float sj[INW];
    for (int i = threadIdx.x; i < INW; i += blockDim.x) sj[i] = g_joined[i];
    __syncthreads();
    int lane = threadIdx.x & 31;
    int row = blockIdx.x * 8 + (threadIdx.x >> 5);
    if (row >= V) return;
    float s = row_dot_516((const float4*)(W_out + (size_t)row * INW),
                          (const float4*)sj, lane);
    s = warp_red(s);
    if (lane == 0) d_out[row] = s + b_out[row];
}

// ---------------- K9: logsumexp over logits
__global__ void k_lse(const float* __restrict__ d_out) {
    __shared__ float red[32];
    int tid = threadIdx.x;
    float m = -1e30f;
    for (int i = tid; i < V; i += 1024) m = fmaxf(m, d_out[i]);
    #pragma unroll
    for (int o = 16; o; o >>= 1) m = fmaxf(m, __shfl_xor_sync(0xffffffffu, m, o));
    if ((tid & 31) == 0) red[tid >> 5] = m;
    __syncthreads();
    if (tid < 32) {
        float t = red[tid];
        #pragma unroll
        for (int o = 16; o; o >>= 1) t = fmaxf(t, __shfl_xor_sync(0xffffffffu, t, o));
        if (tid == 0) red[0] = t;
    }
    __syncthreads();
    m = red[0];
    __syncthreads();
    float ssum = 0.f;
    for (int i = tid; i < V; i += 1024) ssum += expf(d_out[i] - m);
    ssum = warp_red(ssum);
    if ((tid & 31) == 0) red[tid >> 5] = ssum;
    __syncthreads();
    if (tid < 32) {
        float t = red[tid];
        t = warp_red(t);
        if (tid == 0) red[0] = t;
    }
    __syncthreads();
    if (tid == 0) g_lse = m + logf(red[0]);
}

// ---------------- K10: output = logits - lse (in place)
__global__ void k_final(float* __restrict__ d_out) {
    int i = blockIdx.x * blockDim.x + threadIdx.x;
    if (i < V) d_out[i] -= g_lse;
}

extern "C" void kernel_launch(void* const* d_in, const int* in_sizes, int n_in,
                              void* d_out, int out_size) {
    const int*   word  = (const int*)  d_in[0];
    const float* lctx  = (const float*)d_in[1];
    const float* hprev = (const float*)d_in[2];
    const float* enc   = (const float*)d_in[3];
    const float* emb   = (const float*)d_in[4];
    const float* W_ih  = (const float*)d_in[5];
    const float* W_hh  = (const float*)d_in[6];
    const float* b_ih  = (const float*)d_in[7];
    const float* b_hh  = (const float*)d_in[8];
    const float* W_a   = (const float*)d_in[9];
    const float* b_a   = (const float*)d_in[10];
    const float* W_out = (const float*)d_in[11];
    const float* b_out = (const float*)d_in[12];
    float* out = (float*)d_out;

    k_gates  <<<2 * IH_BLOCKS, 256>>>(word, lctx, hprev, emb, W_ih, W_hh, b_ih, b_hh);
    k_gru    <<<1, 1024>>>(hprev, b_a, out);
    k_va     <<<dim3(9, 8), 128>>>(W_a);
    k_scores <<<SL / 8, 256>>>(enc);
    k_softmax<<<1, 1024>>>(out);
    k_context<<<128, 256>>>(enc, out);
    k_join   <<<(H + 255) / 256, 256>>>(out);
    k_out    <<<(V + 7) / 8, 256>>>(W_out, b_out, out);
    k_lse    <<<1, 1024>>>(out);
    k_final  <<<(V + 255) / 256, 256>>>(out);
}